// round 1
// baseline (speedup 1.0000x reference)
#include <cuda_runtime.h>

// Problem constants
#define BSZ  4
#define HH   16
#define SEQ  1024
#define DHD  64
#define DM   1024
#define BHC  (BSZ*HH)          // 64
#define NEGV (-1e9f)

// Static device scratch (allocation-free rule: __device__ globals)
__device__ float g_Q[BHC*SEQ*DHD];                 // (b,h,k,d)  16 MB
__device__ float g_K[BHC*SEQ*DHD];                 // 16 MB
__device__ float g_V[BHC*SEQ*DHD];                 // 16 MB
__device__ float g_S[(size_t)BHC*SEQ*SEQ];         // (bh,q,k)  256 MB
__device__ float g_O[BSZ*SEQ*DM];                  // (b,q,h*64+d) 16 MB

// ---------------------------------------------------------------------------
// K1: QKV GEMM. C(4096x3072) = X(4096x1024) @ W(1024x3072) + b, scattered into
// g_Q/g_K/g_V with (b,h,k,d) layout. 128x128x8 tile, 256 threads, 8x8/thread.
// ---------------------------------------------------------------------------
__global__ __launch_bounds__(256) void qkv_gemm(const float* __restrict__ X,
                                                const float* __restrict__ W,
                                                const float* __restrict__ bias)
{
    const int N = 3*DM, Kd = DM;
    __shared__ float As[8][132];
    __shared__ float Bs[8][128];
    const int t  = threadIdx.x;
    const int m0 = blockIdx.y*128, n0 = blockIdx.x*128;
    const int ty = t>>4, tx = t&15;
    const int arow = t>>1,  ac4 = (t&1)*4;
    const int brow = t>>5,  bc4 = (t&31)*4;

    float acc[8][8];
#pragma unroll
    for (int i=0;i<8;i++)
#pragma unroll
        for (int j=0;j<8;j++) acc[i][j]=0.f;

    for (int kk=0; kk<Kd; kk+=8) {
        float4 a = *(const float4*)&X[(size_t)(m0+arow)*Kd + kk + ac4];
        As[ac4+0][arow]=a.x; As[ac4+1][arow]=a.y;
        As[ac4+2][arow]=a.z; As[ac4+3][arow]=a.w;
        *(float4*)&Bs[brow][bc4] = *(const float4*)&W[(size_t)(kk+brow)*N + n0 + bc4];
        __syncthreads();
#pragma unroll
        for (int k=0;k<8;k++){
            float a0[8], b0[8];
            *(float4*)&a0[0] = *(float4*)&As[k][ty*8];
            *(float4*)&a0[4] = *(float4*)&As[k][ty*8+4];
            *(float4*)&b0[0] = *(float4*)&Bs[k][tx*8];
            *(float4*)&b0[4] = *(float4*)&Bs[k][tx*8+4];
#pragma unroll
            for (int i=0;i<8;i++)
#pragma unroll
                for (int j=0;j<8;j++) acc[i][j] += a0[i]*b0[j];
        }
        __syncthreads();
    }

#pragma unroll
    for (int i=0;i<8;i++){
        const int m = m0 + ty*8 + i;
        const int b = m >> 10, kpos = m & 1023;
#pragma unroll
        for (int j=0;j<8;j++){
            const int n = n0 + tx*8 + j;
            const float v = acc[i][j] + bias[n];
            const int which = n >> 10;
            const int h = (n>>6)&15;
            const int d = n&63;
            float* dst = (which==0) ? g_Q : (which==1 ? g_K : g_V);
            dst[(((b*HH + h)*SEQ) + kpos)*DHD + d] = v;
        }
    }
}

// ---------------------------------------------------------------------------
// K2a: S[bh][q][k] = dot(Q[q], K[k])/8 + (1-clip(mq*mk,0))*NEG
// 64x64 tile over full dh=64. Transposed smem [d][row] with pad.
// ---------------------------------------------------------------------------
__global__ __launch_bounds__(256) void score_kernel(const int* __restrict__ mask)
{
    const int bh = blockIdx.z;
    const int b  = bh >> 4;
    const int q0 = blockIdx.y*64, k0 = blockIdx.x*64;
    __shared__ float Qs[64][68];   // [d][q]
    __shared__ float Ks[64][68];   // [d][k]
    const int t = threadIdx.x;
    const float* Qb = g_Q + (size_t)bh*SEQ*DHD;
    const float* Kb = g_K + (size_t)bh*SEQ*DHD;

#pragma unroll
    for (int i=0;i<4;i++){
        int idx = t + i*256;            // 0..1023
        int row = idx >> 4;
        int c4  = (idx & 15)*4;
        float4 q4 = *(const float4*)&Qb[(q0+row)*DHD + c4];
        Qs[c4+0][row]=q4.x; Qs[c4+1][row]=q4.y; Qs[c4+2][row]=q4.z; Qs[c4+3][row]=q4.w;
        float4 k4 = *(const float4*)&Kb[(k0+row)*DHD + c4];
        Ks[c4+0][row]=k4.x; Ks[c4+1][row]=k4.y; Ks[c4+2][row]=k4.z; Ks[c4+3][row]=k4.w;
    }
    __syncthreads();

    const int ty = t>>4, tx = t&15;
    float acc[4][4];
#pragma unroll
    for (int i=0;i<4;i++)
#pragma unroll
        for (int j=0;j<4;j++) acc[i][j]=0.f;

#pragma unroll 8
    for (int d=0; d<64; d++){
        float4 aq = *(float4*)&Qs[d][ty*4];
        float4 bk = *(float4*)&Ks[d][tx*4];
        float a0[4] = {aq.x,aq.y,aq.z,aq.w};
        float b0[4] = {bk.x,bk.y,bk.z,bk.w};
#pragma unroll
        for (int i=0;i<4;i++)
#pragma unroll
            for (int j=0;j<4;j++) acc[i][j] += a0[i]*b0[j];
    }

    float* Sb = g_S + ((size_t)bh << 20);
#pragma unroll
    for (int i=0;i<4;i++){
        const int q = q0 + ty*4 + i;
        const float mq = (float)mask[b*SEQ + q];
        float4 o;
        float res[4];
#pragma unroll
        for (int j=0;j<4;j++){
            const int k = k0 + tx*4 + j;
            const float mk = (float)mask[b*SEQ + k];
            float mm = mq*mk; mm = mm > 0.f ? mm : 0.f;
            res[j] = acc[i][j]*0.125f + (1.0f - mm)*NEGV;
        }
        o.x=res[0]; o.y=res[1]; o.z=res[2]; o.w=res[3];
        *(float4*)&Sb[(size_t)q*SEQ + k0 + tx*4] = o;
    }
}

// ---------------------------------------------------------------------------
// K2b: in-place row softmax of g_S. One block per row (1024 elems, 256 thr).
// ---------------------------------------------------------------------------
__global__ __launch_bounds__(256) void softmax_kernel()
{
    __shared__ float red_m[8];
    __shared__ float red_s[8];
    const size_t base = (size_t)blockIdx.x * SEQ;
    const int t = threadIdx.x;
    float4 v = *(float4*)&g_S[base + t*4];

    float m = fmaxf(fmaxf(v.x,v.y), fmaxf(v.z,v.w));
#pragma unroll
    for (int o=16;o>0;o>>=1) m = fmaxf(m, __shfl_xor_sync(0xFFFFFFFFu, m, o));
    if ((t&31)==0) red_m[t>>5] = m;
    __syncthreads();
    m = red_m[0];
#pragma unroll
    for (int i=1;i<8;i++) m = fmaxf(m, red_m[i]);

    v.x = __expf(v.x - m); v.y = __expf(v.y - m);
    v.z = __expf(v.z - m); v.w = __expf(v.w - m);
    float s = v.x+v.y+v.z+v.w;
#pragma unroll
    for (int o=16;o>0;o>>=1) s += __shfl_xor_sync(0xFFFFFFFFu, s, o);
    if ((t&31)==0) red_s[t>>5] = s;
    __syncthreads();
    s = 0.f;
#pragma unroll
    for (int i=0;i<8;i++) s += red_s[i];
    const float inv = 1.0f / s;
    v.x*=inv; v.y*=inv; v.z*=inv; v.w*=inv;
    *(float4*)&g_S[base + t*4] = v;
}

// ---------------------------------------------------------------------------
// K2d: attn_out[b][q][k] = mean_h P. Pure strided reads over h.
// ---------------------------------------------------------------------------
__global__ __launch_bounds__(256) void attn_mean(float* __restrict__ out)
{
    const size_t e = ((size_t)blockIdx.x*256 + threadIdx.x) * 4;   // float4 granule
    const int b = (int)(e >> 20);
    const size_t rem = e & ((1u<<20)-1);
    const float* base = g_S + (((size_t)b*HH) << 20) + rem;
    float4 s = {0.f,0.f,0.f,0.f};
#pragma unroll
    for (int h=0; h<HH; h++){
        float4 v = *(const float4*)(base + ((size_t)h<<20));
        s.x+=v.x; s.y+=v.y; s.z+=v.z; s.w+=v.w;
    }
    const float sc = 1.0f/(float)HH;
    s.x*=sc; s.y*=sc; s.z*=sc; s.w*=sc;
    *(float4*)&out[e] = s;
}

// ---------------------------------------------------------------------------
// K2c: O = P(1024x1024) @ V(1024x64) per bh. 64x64 tile, BK=16.
// Output into merged-heads layout g_O(b,q, h*64+d).
// ---------------------------------------------------------------------------
__global__ __launch_bounds__(256) void pv_gemm()
{
    const int bh = blockIdx.z;
    const int b  = bh >> 4, h = bh & 15;
    const int q0 = blockIdx.y*64;
    __shared__ float Ps[16][68];   // [k][q]
    __shared__ float Vs[16][64];   // [k][d]
    const int t = threadIdx.x;
    const float* Pb = g_S + ((size_t)bh << 20);
    const float* Vb = g_V + (size_t)bh*SEQ*DHD;

    const int prow = t>>2,  pc4 = (t&3)*4;
    const int vrow = t>>4,  vc4 = (t&15)*4;
    const int ty = t>>4, tx = t&15;

    float acc[4][4];
#pragma unroll
    for (int i=0;i<4;i++)
#pragma unroll
        for (int j=0;j<4;j++) acc[i][j]=0.f;

    for (int kk=0; kk<SEQ; kk+=16){
        float4 p4 = *(const float4*)&Pb[(size_t)(q0+prow)*SEQ + kk + pc4];
        Ps[pc4+0][prow]=p4.x; Ps[pc4+1][prow]=p4.y;
        Ps[pc4+2][prow]=p4.z; Ps[pc4+3][prow]=p4.w;
        *(float4*)&Vs[vrow][vc4] = *(const float4*)&Vb[(kk+vrow)*DHD + vc4];
        __syncthreads();
#pragma unroll
        for (int k=0;k<16;k++){
            float4 ap = *(float4*)&Ps[k][ty*4];
            float4 bv = *(float4*)&Vs[k][tx*4];
            float a0[4] = {ap.x,ap.y,ap.z,ap.w};
            float b0[4] = {bv.x,bv.y,bv.z,bv.w};
#pragma unroll
            for (int i=0;i<4;i++)
#pragma unroll
                for (int j=0;j<4;j++) acc[i][j] += a0[i]*b0[j];
        }
        __syncthreads();
    }

#pragma unroll
    for (int i=0;i<4;i++){
        const int q = q0 + ty*4 + i;
        float4 o; o.x=acc[i][0]; o.y=acc[i][1]; o.z=acc[i][2]; o.w=acc[i][3];
        *(float4*)&g_O[(((size_t)(b*SEQ + q))*HH + h)*DHD + tx*4] = o;
    }
}

// ---------------------------------------------------------------------------
// K3: tokens_out = tokens + g_O(4096x1024) @ W_proj + b_proj
// Same SGEMM as K1, epilogue adds bias + residual, writes d_out.
// ---------------------------------------------------------------------------
__global__ __launch_bounds__(256) void proj_gemm(const float* __restrict__ tokens,
                                                 const float* __restrict__ W,
                                                 const float* __restrict__ bias,
                                                 float* __restrict__ out)
{
    const int N = DM, Kd = DM;
    __shared__ float As[8][132];
    __shared__ float Bs[8][128];
    const int t  = threadIdx.x;
    const int m0 = blockIdx.y*128, n0 = blockIdx.x*128;
    const int ty = t>>4, tx = t&15;
    const int arow = t>>1,  ac4 = (t&1)*4;
    const int brow = t>>5,  bc4 = (t&31)*4;

    float acc[8][8];
#pragma unroll
    for (int i=0;i<8;i++)
#pragma unroll
        for (int j=0;j<8;j++) acc[i][j]=0.f;

    for (int kk=0; kk<Kd; kk+=8) {
        float4 a = *(const float4*)&g_O[(size_t)(m0+arow)*Kd + kk + ac4];
        As[ac4+0][arow]=a.x; As[ac4+1][arow]=a.y;
        As[ac4+2][arow]=a.z; As[ac4+3][arow]=a.w;
        *(float4*)&Bs[brow][bc4] = *(const float4*)&W[(size_t)(kk+brow)*N + n0 + bc4];
        __syncthreads();
#pragma unroll
        for (int k=0;k<8;k++){
            float a0[8], b0[8];
            *(float4*)&a0[0] = *(float4*)&As[k][ty*8];
            *(float4*)&a0[4] = *(float4*)&As[k][ty*8+4];
            *(float4*)&b0[0] = *(float4*)&Bs[k][tx*8];
            *(float4*)&b0[4] = *(float4*)&Bs[k][tx*8+4];
#pragma unroll
            for (int i=0;i<8;i++)
#pragma unroll
                for (int j=0;j<8;j++) acc[i][j] += a0[i]*b0[j];
        }
        __syncthreads();
    }

#pragma unroll
    for (int i=0;i<8;i++){
        const int m = m0 + ty*8 + i;
#pragma unroll
        for (int j=0;j<8;j++){
            const int n = n0 + tx*8 + j;
            out[(size_t)m*DM + n] = acc[i][j] + bias[n] + tokens[(size_t)m*DM + n];
        }
    }
}

// ---------------------------------------------------------------------------
extern "C" void kernel_launch(void* const* d_in, const int* in_sizes, int n_in,
                              void* d_out, int out_size)
{
    const float* tokens = (const float*)d_in[0];
    const int*   mask   = (const int*)  d_in[1];
    const float* Wqkv   = (const float*)d_in[2];
    const float* bqkv   = (const float*)d_in[3];
    const float* Wproj  = (const float*)d_in[4];
    const float* bproj  = (const float*)d_in[5];
    float* out = (float*)d_out;

    // 1) QKV projection + head split
    qkv_gemm<<<dim3(24, 32), 256>>>(tokens, Wqkv, bqkv);
    // 2) scaled masked scores
    score_kernel<<<dim3(16, 16, BHC), 256>>>(mask);
    // 3) softmax rows (in place)
    softmax_kernel<<<BHC*SEQ, 256>>>();
    // 4) attn mean over heads -> second output half
    attn_mean<<<(BSZ*SEQ*SEQ/4)/256, 256>>>(out + (size_t)BSZ*SEQ*DM);
    // 5) P @ V -> merged heads
    pv_gemm<<<dim3(1, 16, BHC), 256>>>();
    // 6) output projection + bias + residual -> first output half
    proj_gemm<<<dim3(8, 32), 256>>>(tokens, Wproj, bproj, out);
}

// round 4
// speedup vs baseline: 3.6827x; 3.6827x over previous
#include <cuda_runtime.h>
#include <cuda_bf16.h>
#include <cstdint>

#define BSZ  4
#define HH   16
#define SEQ  1024
#define DHD  64
#define DM   1024
#define NEGV (-1e9f)

// ---------------- device scratch (allocation-free rule) ----------------
__device__ float g_Q[64*1024*64];            // [bh][kpos][d] 16MB
__device__ float g_K[64*1024*64];
__device__ float g_V[64*1024*64];
__device__ float g_S[(size_t)64*1024*1024];  // [bh][q][k] 256MB
__device__ float g_O[4096*1024];             // [m][h*64+d]  16MB

// ---------------- mma helpers (arch-portable HMMA path) ----------------
__device__ __forceinline__ uint32_t smem_u32(const void* p){
    uint32_t a;
    asm("{ .reg .u64 t; cvta.to.shared.u64 t, %1; cvt.u32.u64 %0, t; }" : "=r"(a) : "l"(p));
    return a;
}
__device__ __forceinline__ void ldsm4(uint32_t* r, uint32_t addr){
    asm volatile("ldmatrix.sync.aligned.m8n8.x4.shared.b16 {%0,%1,%2,%3}, [%4];"
        : "=r"(r[0]), "=r"(r[1]), "=r"(r[2]), "=r"(r[3]) : "r"(addr));
}
__device__ __forceinline__ void ldsm4t(uint32_t* r, uint32_t addr){
    asm volatile("ldmatrix.sync.aligned.m8n8.x4.trans.shared.b16 {%0,%1,%2,%3}, [%4];"
        : "=r"(r[0]), "=r"(r[1]), "=r"(r[2]), "=r"(r[3]) : "r"(addr));
}
__device__ __forceinline__ void mma16816(float* d, const uint32_t* a, const uint32_t* b){
    asm volatile("mma.sync.aligned.m16n8k16.row.col.f32.bf16.bf16.f32 "
        "{%0,%1,%2,%3}, {%4,%5,%6,%7}, {%8,%9}, {%0,%1,%2,%3};"
        : "+f"(d[0]), "+f"(d[1]), "+f"(d[2]), "+f"(d[3])
        : "r"(a[0]), "r"(a[1]), "r"(a[2]), "r"(a[3]), "r"(b[0]), "r"(b[1]));
}
// split fp32x4 -> bf16 hi/lo pairs, 8B stores
__device__ __forceinline__ void split_store4(float4 v, __nv_bfloat16* hi, __nv_bfloat16* lo){
    __nv_bfloat16 h0 = __float2bfloat16_rn(v.x), h1 = __float2bfloat16_rn(v.y);
    __nv_bfloat16 h2 = __float2bfloat16_rn(v.z), h3 = __float2bfloat16_rn(v.w);
    __nv_bfloat16 l0 = __float2bfloat16_rn(v.x - __bfloat162float(h0));
    __nv_bfloat16 l1 = __float2bfloat16_rn(v.y - __bfloat162float(h1));
    __nv_bfloat16 l2 = __float2bfloat16_rn(v.z - __bfloat162float(h2));
    __nv_bfloat16 l3 = __float2bfloat16_rn(v.w - __bfloat162float(h3));
    __nv_bfloat162 hA{h0,h1}, hB{h2,h3}, lA{l0,l1}, lB{l2,l3};
    uint2 hu{*(uint32_t*)&hA, *(uint32_t*)&hB};
    uint2 lu{*(uint32_t*)&lA, *(uint32_t*)&lB};
    *(uint2*)hi = hu;
    *(uint2*)lo = lu;
}

// ---------------------------------------------------------------------------
// K1: QKV GEMM  C(4096x3072) = X @ Wqkv + b  -> scatter to g_Q/g_K/g_V
// BM=128 BN=128 BK=32, 256 thr, warp grid 2m x 4n, warp tile 64x32.
// ---------------------------------------------------------------------------
__global__ __launch_bounds__(256) void qkv_hmma(const float* __restrict__ X,
                                                const float* __restrict__ W,
                                                const float* __restrict__ bias)
{
    __shared__ __align__(16) __nv_bfloat16 sAh[128*40], sAl[128*40];
    __shared__ __align__(16) __nv_bfloat16 sBh[32*136], sBl[32*136];
    const int t = threadIdx.x, lane = t&31, wid = t>>5;
    const int m0 = blockIdx.y*128, n0 = blockIdx.x*128;
    const int wm = wid>>2, wn = wid&3;
    const uint32_t aBH = smem_u32(sAh), aBL = smem_u32(sAl);
    const uint32_t bBH = smem_u32(sBh), bBL = smem_u32(sBl);
    const int arow = ((lane>>3)&1)*8 + (lane&7);
    const int acol = (lane>>4)*8;
    const int bkrow = ((lane>>3)&1)*8 + (lane&7);
    const int bnsel = (lane>>4)*8;

    float acc[4][4][4];
#pragma unroll
    for (int a=0;a<4;a++)
#pragma unroll
        for (int b=0;b<4;b++)
#pragma unroll
            for (int c=0;c<4;c++) acc[a][b][c]=0.f;

    for (int ck=0; ck<32; ck++){
        const int kk = ck*32;
#pragma unroll
        for (int j=0;j<4;j++){
            int i = t + j*256;
            int r = i>>3, c = (i&7)*4;
            float4 v = *(const float4*)&X[(size_t)(m0+r)*DM + kk + c];
            split_store4(v, sAh + r*40 + c, sAl + r*40 + c);
        }
#pragma unroll
        for (int j=0;j<4;j++){
            int i = t + j*256;
            int r = i>>5, c = (i&31)*4;
            float4 v = *(const float4*)&W[(size_t)(kk+r)*3072 + n0 + c];
            split_store4(v, sBh + r*136 + c, sBl + r*136 + c);
        }
        __syncthreads();
#pragma unroll
        for (int ks=0; ks<2; ks++){
            uint32_t ah[4][4], al[4][4];
#pragma unroll
            for (int mf=0; mf<4; mf++){
                int eo = (wm*64 + mf*16 + arow)*40 + ks*16 + acol;
                ldsm4(ah[mf], aBH + eo*2);
                ldsm4(al[mf], aBL + eo*2);
            }
            uint32_t bh[2][4], bl[2][4];
#pragma unroll
            for (int p=0;p<2;p++){
                int eo = (ks*16 + bkrow)*136 + wn*32 + p*16 + bnsel;
                ldsm4t(bh[p], bBH + eo*2);
                ldsm4t(bl[p], bBL + eo*2);
            }
#pragma unroll
            for (int mf=0;mf<4;mf++)
#pragma unroll
                for (int nf=0;nf<4;nf++){
                    const uint32_t* bhp = &bh[nf>>1][(nf&1)*2];
                    const uint32_t* blp = &bl[nf>>1][(nf&1)*2];
                    mma16816(acc[mf][nf], ah[mf], bhp);
                    mma16816(acc[mf][nf], ah[mf], blp);
                    mma16816(acc[mf][nf], al[mf], bhp);
                }
        }
        __syncthreads();
    }

    const int g = lane>>2, tt = lane&3;
#pragma unroll
    for (int mf=0;mf<4;mf++){
        const int m = m0 + wm*64 + mf*16 + g;
        const int b = m>>10, kpos = m&1023;
#pragma unroll
        for (int nf=0;nf<4;nf++){
            const int n = n0 + wn*32 + nf*8 + tt*2;
            const int which = n>>10, h = (n>>6)&15, d = n&63;
            float* dst = which==0 ? g_Q : (which==1 ? g_K : g_V);
            const size_t base0 = (((size_t)(b*HH+h))*SEQ + kpos)*DHD + d;
            const float bi0 = bias[n], bi1 = bias[n+1];
            float2 v0{acc[mf][nf][0]+bi0, acc[mf][nf][1]+bi1};
            float2 v1{acc[mf][nf][2]+bi0, acc[mf][nf][3]+bi1};
            *(float2*)&dst[base0]           = v0;
            *(float2*)&dst[base0 + 8*DHD]   = v1;   // row +8 => kpos+8
        }
    }
}

// ---------------------------------------------------------------------------
// K2a: scores S = (Q K^T)/8 + mask.  BM=128(q) BN=128(k), d chunked 2x32.
// Static smem only (~41KB) so no cudaFuncSetAttribute needed.
// ---------------------------------------------------------------------------
__global__ __launch_bounds__(256) void score_hmma(const int* __restrict__ mask)
{
    __shared__ __align__(16) __nv_bfloat16 sQh[128*40], sQl[128*40];
    __shared__ __align__(16) __nv_bfloat16 sKh[128*40], sKl[128*40];
    __shared__ int sm_mq[128], sm_mk[128];

    const int t = threadIdx.x, lane = t&31, wid = t>>5;
    const int bh = blockIdx.z, b = bh>>4;
    const int q0 = blockIdx.y*128, k0 = blockIdx.x*128;
    const int wm = wid>>2, wn = wid&3;
    const uint32_t qBH = smem_u32(sQh), qBL = smem_u32(sQl);
    const uint32_t kBH = smem_u32(sKh), kBL = smem_u32(sKl);

    if (t < 128){ sm_mq[t] = mask[b*SEQ + q0 + t]; }
    else        { sm_mk[t-128] = mask[b*SEQ + k0 + (t-128)]; }

    const size_t qb = (size_t)bh*SEQ*DHD;
    const int arow = ((lane>>3)&1)*8 + (lane&7);
    const int acol = (lane>>4)*8;
    const int bnrow = (lane>=16?8:0) + (lane&7);
    const int bkcol = ((lane>>3)&1)*8;

    float acc[4][4][4];
#pragma unroll
    for (int a=0;a<4;a++)
#pragma unroll
        for (int bb=0;bb<4;bb++)
#pragma unroll
            for (int c=0;c<4;c++) acc[a][bb][c]=0.f;

#pragma unroll
    for (int ck=0; ck<2; ck++){
        const int kk = ck*32;
#pragma unroll
        for (int j=0;j<4;j++){
            int i = t + j*256;
            int r = i>>3, c = (i&7)*4;
            float4 vq = *(const float4*)&g_Q[qb + (size_t)(q0+r)*DHD + kk + c];
            split_store4(vq, sQh + r*40 + c, sQl + r*40 + c);
            float4 vk = *(const float4*)&g_K[qb + (size_t)(k0+r)*DHD + kk + c];
            split_store4(vk, sKh + r*40 + c, sKl + r*40 + c);
        }
        __syncthreads();
#pragma unroll
        for (int ks=0; ks<2; ks++){
            uint32_t ah[4][4], al[4][4];
#pragma unroll
            for (int mf=0; mf<4; mf++){
                int eo = (wm*64 + mf*16 + arow)*40 + ks*16 + acol;
                ldsm4(ah[mf], qBH + eo*2);
                ldsm4(al[mf], qBL + eo*2);
            }
            uint32_t bhh[2][4], bll[2][4];
#pragma unroll
            for (int p=0;p<2;p++){
                int eo = (wn*32 + p*16 + bnrow)*40 + ks*16 + bkcol;
                ldsm4(bhh[p], kBH + eo*2);
                ldsm4(bll[p], kBL + eo*2);
            }
#pragma unroll
            for (int mf=0;mf<4;mf++)
#pragma unroll
                for (int nf=0;nf<4;nf++){
                    const uint32_t* bhp = &bhh[nf>>1][(nf&1)*2];
                    const uint32_t* blp = &bll[nf>>1][(nf&1)*2];
                    mma16816(acc[mf][nf], ah[mf], bhp);
                    mma16816(acc[mf][nf], ah[mf], blp);
                    mma16816(acc[mf][nf], al[mf], bhp);
                }
        }
        __syncthreads();
    }

    const int g = lane>>2, tt = lane&3;
    float* Sb = g_S + ((size_t)bh<<20);
#pragma unroll
    for (int mf=0;mf<4;mf++){
        const int qr = wm*64 + mf*16 + g;
        const float mq0 = (float)sm_mq[qr];
        const float mq1 = (float)sm_mq[qr+8];
#pragma unroll
        for (int nf=0;nf<4;nf++){
            const int kc = wn*32 + nf*8 + tt*2;
            const float mk0 = (float)sm_mk[kc], mk1 = (float)sm_mk[kc+1];
            float p00 = fmaxf(mq0*mk0,0.f), p01 = fmaxf(mq0*mk1,0.f);
            float p10 = fmaxf(mq1*mk0,0.f), p11 = fmaxf(mq1*mk1,0.f);
            float2 v0{acc[mf][nf][0]*0.125f + (1.f-p00)*NEGV,
                      acc[mf][nf][1]*0.125f + (1.f-p01)*NEGV};
            float2 v1{acc[mf][nf][2]*0.125f + (1.f-p10)*NEGV,
                      acc[mf][nf][3]*0.125f + (1.f-p11)*NEGV};
            *(float2*)&Sb[(size_t)(q0+qr)*SEQ + k0 + kc]     = v0;
            *(float2*)&Sb[(size_t)(q0+qr+8)*SEQ + k0 + kc]   = v1;
        }
    }
}

// ---------------------------------------------------------------------------
// K2b: in-place row softmax of g_S (fp32).
// ---------------------------------------------------------------------------
__global__ __launch_bounds__(256) void softmax_kernel()
{
    __shared__ float red_m[8], red_s[8];
    const size_t base = (size_t)blockIdx.x * SEQ;
    const int t = threadIdx.x;
    float4 v = *(float4*)&g_S[base + t*4];
    float m = fmaxf(fmaxf(v.x,v.y), fmaxf(v.z,v.w));
#pragma unroll
    for (int o=16;o>0;o>>=1) m = fmaxf(m, __shfl_xor_sync(0xFFFFFFFFu, m, o));
    if ((t&31)==0) red_m[t>>5] = m;
    __syncthreads();
    m = red_m[0];
#pragma unroll
    for (int i=1;i<8;i++) m = fmaxf(m, red_m[i]);
    v.x = __expf(v.x-m); v.y = __expf(v.y-m); v.z = __expf(v.z-m); v.w = __expf(v.w-m);
    float s = v.x+v.y+v.z+v.w;
#pragma unroll
    for (int o=16;o>0;o>>=1) s += __shfl_xor_sync(0xFFFFFFFFu, s, o);
    if ((t&31)==0) red_s[t>>5] = s;
    __syncthreads();
    s = 0.f;
#pragma unroll
    for (int i=0;i<8;i++) s += red_s[i];
    const float inv = 1.0f/s;
    v.x*=inv; v.y*=inv; v.z*=inv; v.w*=inv;
    *(float4*)&g_S[base + t*4] = v;
}

// ---------------------------------------------------------------------------
// K2d: attn_out = mean over heads of P.
// ---------------------------------------------------------------------------
__global__ __launch_bounds__(256) void attn_mean(float* __restrict__ out)
{
    const size_t e = ((size_t)blockIdx.x*256 + threadIdx.x) * 4;
    const int b = (int)(e >> 20);
    const size_t rem = e & ((1u<<20)-1);
    const float* base = g_S + (((size_t)b*HH) << 20) + rem;
    float4 s{0.f,0.f,0.f,0.f};
#pragma unroll
    for (int h=0; h<HH; h++){
        float4 v = *(const float4*)(base + ((size_t)h<<20));
        s.x+=v.x; s.y+=v.y; s.z+=v.z; s.w+=v.w;
    }
    const float sc = 1.0f/(float)HH;
    s.x*=sc; s.y*=sc; s.z*=sc; s.w*=sc;
    *(float4*)&out[e] = s;
}

// ---------------------------------------------------------------------------
// K2c: O = P @ V per bh -> merged heads g_O.  BM=128 BN=64 BK=32.
// warp grid 4m x 2n, warp tile 32x32.
// ---------------------------------------------------------------------------
__global__ __launch_bounds__(256) void pv_hmma()
{
    __shared__ __align__(16) __nv_bfloat16 sAh[128*40], sAl[128*40];
    __shared__ __align__(16) __nv_bfloat16 sBh[32*72], sBl[32*72];
    const int t = threadIdx.x, lane = t&31, wid = t>>5;
    const int bh = blockIdx.y, b = bh>>4, h = bh&15;
    const int q0 = blockIdx.x*128;
    const int wm = wid>>1, wn = wid&1;
    const uint32_t aBH = smem_u32(sAh), aBL = smem_u32(sAl);
    const uint32_t bBH = smem_u32(sBh), bBL = smem_u32(sBl);
    const int arow = ((lane>>3)&1)*8 + (lane&7);
    const int acol = (lane>>4)*8;
    const int bkrow = ((lane>>3)&1)*8 + (lane&7);
    const int bnsel = (lane>>4)*8;
    const size_t pb = (size_t)bh<<20;
    const size_t vb = (size_t)bh*SEQ*DHD;

    float acc[2][4][4];
#pragma unroll
    for (int a=0;a<2;a++)
#pragma unroll
        for (int bb=0;bb<4;bb++)
#pragma unroll
            for (int c=0;c<4;c++) acc[a][bb][c]=0.f;

    for (int ck=0; ck<32; ck++){
        const int kk = ck*32;
#pragma unroll
        for (int j=0;j<4;j++){
            int i = t + j*256;
            int r = i>>3, c = (i&7)*4;
            float4 v = *(const float4*)&g_S[pb + (size_t)(q0+r)*SEQ + kk + c];
            split_store4(v, sAh + r*40 + c, sAl + r*40 + c);
        }
#pragma unroll
        for (int j=0;j<2;j++){
            int i = t + j*256;
            int r = i>>4, c = (i&15)*4;
            float4 v = *(const float4*)&g_V[vb + (size_t)(kk+r)*DHD + c];
            split_store4(v, sBh + r*72 + c, sBl + r*72 + c);
        }
        __syncthreads();
#pragma unroll
        for (int ks=0; ks<2; ks++){
            uint32_t ah[2][4], al[2][4];
#pragma unroll
            for (int mf=0; mf<2; mf++){
                int eo = (wm*32 + mf*16 + arow)*40 + ks*16 + acol;
                ldsm4(ah[mf], aBH + eo*2);
                ldsm4(al[mf], aBL + eo*2);
            }
            uint32_t bhh[2][4], bll[2][4];
#pragma unroll
            for (int p=0;p<2;p++){
                int eo = (ks*16 + bkrow)*72 + wn*32 + p*16 + bnsel;
                ldsm4t(bhh[p], bBH + eo*2);
                ldsm4t(bll[p], bBL + eo*2);
            }
#pragma unroll
            for (int mf=0;mf<2;mf++)
#pragma unroll
                for (int nf=0;nf<4;nf++){
                    const uint32_t* bhp = &bhh[nf>>1][(nf&1)*2];
                    const uint32_t* blp = &bll[nf>>1][(nf&1)*2];
                    mma16816(acc[mf][nf], ah[mf], bhp);
                    mma16816(acc[mf][nf], ah[mf], blp);
                    mma16816(acc[mf][nf], al[mf], bhp);
                }
        }
        __syncthreads();
    }

    const int g = lane>>2, tt = lane&3;
#pragma unroll
    for (int mf=0;mf<2;mf++){
        const int q = q0 + wm*32 + mf*16 + g;
        const size_t row0 = ((size_t)(b*SEQ + q))*DM + h*DHD;
#pragma unroll
        for (int nf=0;nf<4;nf++){
            const int d = wn*32 + nf*8 + tt*2;
            *(float2*)&g_O[row0 + d]           = float2{acc[mf][nf][0], acc[mf][nf][1]};
            *(float2*)&g_O[row0 + 8*DM + d]    = float2{acc[mf][nf][2], acc[mf][nf][3]};
        }
    }
}

// ---------------------------------------------------------------------------
// K3: out = tokens + O @ Wproj + b.  Same shape as qkv (N=1024).
// ---------------------------------------------------------------------------
__global__ __launch_bounds__(256) void proj_hmma(const float* __restrict__ tokens,
                                                 const float* __restrict__ W,
                                                 const float* __restrict__ bias,
                                                 float* __restrict__ out)
{
    __shared__ __align__(16) __nv_bfloat16 sAh[128*40], sAl[128*40];
    __shared__ __align__(16) __nv_bfloat16 sBh[32*136], sBl[32*136];
    const int t = threadIdx.x, lane = t&31, wid = t>>5;
    const int m0 = blockIdx.y*128, n0 = blockIdx.x*128;
    const int wm = wid>>2, wn = wid&3;
    const uint32_t aBH = smem_u32(sAh), aBL = smem_u32(sAl);
    const uint32_t bBH = smem_u32(sBh), bBL = smem_u32(sBl);
    const int arow = ((lane>>3)&1)*8 + (lane&7);
    const int acol = (lane>>4)*8;
    const int bkrow = ((lane>>3)&1)*8 + (lane&7);
    const int bnsel = (lane>>4)*8;

    float acc[4][4][4];
#pragma unroll
    for (int a=0;a<4;a++)
#pragma unroll
        for (int b=0;b<4;b++)
#pragma unroll
            for (int c=0;c<4;c++) acc[a][b][c]=0.f;

    for (int ck=0; ck<32; ck++){
        const int kk = ck*32;
#pragma unroll
        for (int j=0;j<4;j++){
            int i = t + j*256;
            int r = i>>3, c = (i&7)*4;
            float4 v = *(const float4*)&g_O[(size_t)(m0+r)*DM + kk + c];
            split_store4(v, sAh + r*40 + c, sAl + r*40 + c);
        }
#pragma unroll
        for (int j=0;j<4;j++){
            int i = t + j*256;
            int r = i>>5, c = (i&31)*4;
            float4 v = *(const float4*)&W[(size_t)(kk+r)*DM + n0 + c];
            split_store4(v, sBh + r*136 + c, sBl + r*136 + c);
        }
        __syncthreads();
#pragma unroll
        for (int ks=0; ks<2; ks++){
            uint32_t ah[4][4], al[4][4];
#pragma unroll
            for (int mf=0; mf<4; mf++){
                int eo = (wm*64 + mf*16 + arow)*40 + ks*16 + acol;
                ldsm4(ah[mf], aBH + eo*2);
                ldsm4(al[mf], aBL + eo*2);
            }
            uint32_t bh[2][4], bl[2][4];
#pragma unroll
            for (int p=0;p<2;p++){
                int eo = (ks*16 + bkrow)*136 + wn*32 + p*16 + bnsel;
                ldsm4t(bh[p], bBH + eo*2);
                ldsm4t(bl[p], bBL + eo*2);
            }
#pragma unroll
            for (int mf=0;mf<4;mf++)
#pragma unroll
                for (int nf=0;nf<4;nf++){
                    const uint32_t* bhp = &bh[nf>>1][(nf&1)*2];
                    const uint32_t* blp = &bl[nf>>1][(nf&1)*2];
                    mma16816(acc[mf][nf], ah[mf], bhp);
                    mma16816(acc[mf][nf], ah[mf], blp);
                    mma16816(acc[mf][nf], al[mf], bhp);
                }
        }
        __syncthreads();
    }

    const int g = lane>>2, tt = lane&3;
#pragma unroll
    for (int mf=0;mf<4;mf++){
        const int m = m0 + wm*64 + mf*16 + g;
#pragma unroll
        for (int nf=0;nf<4;nf++){
            const int n = n0 + wn*32 + nf*8 + tt*2;
            const float bi0 = bias[n], bi1 = bias[n+1];
            float2 t0 = *(const float2*)&tokens[(size_t)m*DM + n];
            float2 t1 = *(const float2*)&tokens[(size_t)(m+8)*DM + n];
            *(float2*)&out[(size_t)m*DM + n] =
                float2{acc[mf][nf][0]+bi0+t0.x, acc[mf][nf][1]+bi1+t0.y};
            *(float2*)&out[(size_t)(m+8)*DM + n] =
                float2{acc[mf][nf][2]+bi0+t1.x, acc[mf][nf][3]+bi1+t1.y};
        }
    }
}

// ---------------------------------------------------------------------------
extern "C" void kernel_launch(void* const* d_in, const int* in_sizes, int n_in,
                              void* d_out, int out_size)
{
    const float* tokens = (const float*)d_in[0];
    const int*   mask   = (const int*)  d_in[1];
    const float* Wqkv   = (const float*)d_in[2];
    const float* bqkv   = (const float*)d_in[3];
    const float* Wproj  = (const float*)d_in[4];
    const float* bproj  = (const float*)d_in[5];
    float* out = (float*)d_out;

    qkv_hmma<<<dim3(24, 32), 256>>>(tokens, Wqkv, bqkv);
    score_hmma<<<dim3(8, 8, 64), 256>>>(mask);
    softmax_kernel<<<64*1024, 256>>>();
    attn_mean<<<4096, 256>>>(out + (size_t)BSZ*SEQ*DM);
    pv_hmma<<<dim3(8, 64), 256>>>();
    proj_hmma<<<dim3(8, 32), 256>>>(tokens, Wproj, bproj, out);
}

// round 8
// speedup vs baseline: 4.2644x; 1.1580x over previous
#include <cuda_runtime.h>
#include <cuda_bf16.h>
#include <cuda_fp16.h>
#include <cstdint>

#define BSZ  4
#define HH   16
#define SEQ  1024
#define DHD  64
#define DM   1024
#define NEGV (-1e9f)

// ---------------- device scratch (allocation-free rule) ----------------
__device__ float  g_Q[64*1024*64];            // [bh][kpos][d] 16MB
__device__ float  g_K[64*1024*64];
__device__ float  g_V[64*1024*64];
__device__ float  g_S[(size_t)64*1024*1024];  // [bh][q][k] scores fp32, 256MB
__device__ __half g_P[(size_t)64*1024*1024];  // [bh][q][k] probs fp16, 128MB
__device__ float  g_O[4096*1024];             // [m][h*64+d]  16MB

// ---------------- mma helpers (arch-portable HMMA path) ----------------
__device__ __forceinline__ uint32_t smem_u32(const void* p){
    uint32_t a;
    asm("{ .reg .u64 t; cvta.to.shared.u64 t, %1; cvt.u32.u64 %0, t; }" : "=r"(a) : "l"(p));
    return a;
}
__device__ __forceinline__ void ldsm4(uint32_t* r, uint32_t addr){
    asm volatile("ldmatrix.sync.aligned.m8n8.x4.shared.b16 {%0,%1,%2,%3}, [%4];"
        : "=r"(r[0]), "=r"(r[1]), "=r"(r[2]), "=r"(r[3]) : "r"(addr));
}
__device__ __forceinline__ void ldsm4t(uint32_t* r, uint32_t addr){
    asm volatile("ldmatrix.sync.aligned.m8n8.x4.trans.shared.b16 {%0,%1,%2,%3}, [%4];"
        : "=r"(r[0]), "=r"(r[1]), "=r"(r[2]), "=r"(r[3]) : "r"(addr));
}
__device__ __forceinline__ void mma16816(float* d, const uint32_t* a, const uint32_t* b){
    asm volatile("mma.sync.aligned.m16n8k16.row.col.f32.bf16.bf16.f32 "
        "{%0,%1,%2,%3}, {%4,%5,%6,%7}, {%8,%9}, {%0,%1,%2,%3};"
        : "+f"(d[0]), "+f"(d[1]), "+f"(d[2]), "+f"(d[3])
        : "r"(a[0]), "r"(a[1]), "r"(a[2]), "r"(a[3]), "r"(b[0]), "r"(b[1]));
}
__device__ __forceinline__ void mma16816h(float* d, const uint32_t* a, const uint32_t* b){
    asm volatile("mma.sync.aligned.m16n8k16.row.col.f32.f16.f16.f32 "
        "{%0,%1,%2,%3}, {%4,%5,%6,%7}, {%8,%9}, {%0,%1,%2,%3};"
        : "+f"(d[0]), "+f"(d[1]), "+f"(d[2]), "+f"(d[3])
        : "r"(a[0]), "r"(a[1]), "r"(a[2]), "r"(a[3]), "r"(b[0]), "r"(b[1]));
}
// split fp32x4 -> bf16 hi/lo pairs, 8B stores
__device__ __forceinline__ void split_store4(float4 v, __nv_bfloat16* hi, __nv_bfloat16* lo){
    __nv_bfloat16 h0 = __float2bfloat16_rn(v.x), h1 = __float2bfloat16_rn(v.y);
    __nv_bfloat16 h2 = __float2bfloat16_rn(v.z), h3 = __float2bfloat16_rn(v.w);
    __nv_bfloat16 l0 = __float2bfloat16_rn(v.x - __bfloat162float(h0));
    __nv_bfloat16 l1 = __float2bfloat16_rn(v.y - __bfloat162float(h1));
    __nv_bfloat16 l2 = __float2bfloat16_rn(v.z - __bfloat162float(h2));
    __nv_bfloat16 l3 = __float2bfloat16_rn(v.w - __bfloat162float(h3));
    __nv_bfloat162 hA{h0,h1}, hB{h2,h3}, lA{l0,l1}, lB{l2,l3};
    uint2 hu{*(uint32_t*)&hA, *(uint32_t*)&hB};
    uint2 lu{*(uint32_t*)&lA, *(uint32_t*)&lB};
    *(uint2*)hi = hu;
    *(uint2*)lo = lu;
}
// split fp32x4 -> fp16 hi/lo pairs
__device__ __forceinline__ void split_store4h(float4 v, __half* hi, __half* lo){
    __half h0 = __float2half_rn(v.x), h1 = __float2half_rn(v.y);
    __half h2 = __float2half_rn(v.z), h3 = __float2half_rn(v.w);
    __half l0 = __float2half_rn(v.x - __half2float(h0));
    __half l1 = __float2half_rn(v.y - __half2float(h1));
    __half l2 = __float2half_rn(v.z - __half2float(h2));
    __half l3 = __float2half_rn(v.w - __half2float(h3));
    __half2 hA{h0,h1}, hB{h2,h3}, lA{l0,l1}, lB{l2,l3};
    uint2 hu{*(uint32_t*)&hA, *(uint32_t*)&hB};
    uint2 lu{*(uint32_t*)&lA, *(uint32_t*)&lB};
    *(uint2*)hi = hu;
    *(uint2*)lo = lu;
}

// ---------------------------------------------------------------------------
// K1: QKV GEMM (identical to round-4 passing version).
// ---------------------------------------------------------------------------
__global__ __launch_bounds__(256) void qkv_hmma(const float* __restrict__ X,
                                                const float* __restrict__ W,
                                                const float* __restrict__ bias)
{
    __shared__ __align__(16) __nv_bfloat16 sAh[128*40], sAl[128*40];
    __shared__ __align__(16) __nv_bfloat16 sBh[32*136], sBl[32*136];
    const int t = threadIdx.x, lane = t&31, wid = t>>5;
    const int m0 = blockIdx.y*128, n0 = blockIdx.x*128;
    const int wm = wid>>2, wn = wid&3;
    const uint32_t aBH = smem_u32(sAh), aBL = smem_u32(sAl);
    const uint32_t bBH = smem_u32(sBh), bBL = smem_u32(sBl);
    const int arow = ((lane>>3)&1)*8 + (lane&7);
    const int acol = (lane>>4)*8;
    const int bkrow = ((lane>>3)&1)*8 + (lane&7);
    const int bnsel = (lane>>4)*8;

    float acc[4][4][4];
#pragma unroll
    for (int a=0;a<4;a++)
#pragma unroll
        for (int b=0;b<4;b++)
#pragma unroll
            for (int c=0;c<4;c++) acc[a][b][c]=0.f;

    for (int ck=0; ck<32; ck++){
        const int kk = ck*32;
#pragma unroll
        for (int j=0;j<4;j++){
            int i = t + j*256;
            int r = i>>3, c = (i&7)*4;
            float4 v = *(const float4*)&X[(size_t)(m0+r)*DM + kk + c];
            split_store4(v, sAh + r*40 + c, sAl + r*40 + c);
        }
#pragma unroll
        for (int j=0;j<4;j++){
            int i = t + j*256;
            int r = i>>5, c = (i&31)*4;
            float4 v = *(const float4*)&W[(size_t)(kk+r)*3072 + n0 + c];
            split_store4(v, sBh + r*136 + c, sBl + r*136 + c);
        }
        __syncthreads();
#pragma unroll
        for (int ks=0; ks<2; ks++){
            uint32_t ah[4][4], al[4][4];
#pragma unroll
            for (int mf=0; mf<4; mf++){
                int eo = (wm*64 + mf*16 + arow)*40 + ks*16 + acol;
                ldsm4(ah[mf], aBH + eo*2);
                ldsm4(al[mf], aBL + eo*2);
            }
            uint32_t bh[2][4], bl[2][4];
#pragma unroll
            for (int p=0;p<2;p++){
                int eo = (ks*16 + bkrow)*136 + wn*32 + p*16 + bnsel;
                ldsm4t(bh[p], bBH + eo*2);
                ldsm4t(bl[p], bBL + eo*2);
            }
#pragma unroll
            for (int mf=0;mf<4;mf++)
#pragma unroll
                for (int nf=0;nf<4;nf++){
                    const uint32_t* bhp = &bh[nf>>1][(nf&1)*2];
                    const uint32_t* blp = &bl[nf>>1][(nf&1)*2];
                    mma16816(acc[mf][nf], ah[mf], bhp);
                    mma16816(acc[mf][nf], ah[mf], blp);
                    mma16816(acc[mf][nf], al[mf], bhp);
                }
        }
        __syncthreads();
    }

    const int g = lane>>2, tt = lane&3;
#pragma unroll
    for (int mf=0;mf<4;mf++){
        const int m = m0 + wm*64 + mf*16 + g;
        const int b = m>>10, kpos = m&1023;
#pragma unroll
        for (int nf=0;nf<4;nf++){
            const int n = n0 + wn*32 + nf*8 + tt*2;
            const int which = n>>10, h = (n>>6)&15, d = n&63;
            float* dst = which==0 ? g_Q : (which==1 ? g_K : g_V);
            const size_t base0 = (((size_t)(b*HH+h))*SEQ + kpos)*DHD + d;
            const float bi0 = bias[n], bi1 = bias[n+1];
            *(float2*)&dst[base0]         = float2{acc[mf][nf][0]+bi0, acc[mf][nf][1]+bi1};
            *(float2*)&dst[base0 + 8*DHD] = float2{acc[mf][nf][2]+bi0, acc[mf][nf][3]+bi1};
        }
    }
}

// ---------------------------------------------------------------------------
// K2a: scores S = (Q K^T)/8 + mask (identical to round-4 passing version).
// ---------------------------------------------------------------------------
__global__ __launch_bounds__(256) void score_hmma(const int* __restrict__ mask)
{
    __shared__ __align__(16) __nv_bfloat16 sQh[128*40], sQl[128*40];
    __shared__ __align__(16) __nv_bfloat16 sKh[128*40], sKl[128*40];
    __shared__ int sm_mq[128], sm_mk[128];

    const int t = threadIdx.x, lane = t&31, wid = t>>5;
    const int bh = blockIdx.z, b = bh>>4;
    const int q0 = blockIdx.y*128, k0 = blockIdx.x*128;
    const int wm = wid>>2, wn = wid&3;
    const uint32_t qBH = smem_u32(sQh), qBL = smem_u32(sQl);
    const uint32_t kBH = smem_u32(sKh), kBL = smem_u32(sKl);

    if (t < 128){ sm_mq[t] = mask[b*SEQ + q0 + t]; }
    else        { sm_mk[t-128] = mask[b*SEQ + k0 + (t-128)]; }

    const size_t qb = (size_t)bh*SEQ*DHD;
    const int arow = ((lane>>3)&1)*8 + (lane&7);
    const int acol = (lane>>4)*8;
    const int bnrow = (lane>=16?8:0) + (lane&7);
    const int bkcol = ((lane>>3)&1)*8;

    float acc[4][4][4];
#pragma unroll
    for (int a=0;a<4;a++)
#pragma unroll
        for (int bb=0;bb<4;bb++)
#pragma unroll
            for (int c=0;c<4;c++) acc[a][bb][c]=0.f;

#pragma unroll
    for (int ck=0; ck<2; ck++){
        const int kk = ck*32;
#pragma unroll
        for (int j=0;j<4;j++){
            int i = t + j*256;
            int r = i>>3, c = (i&7)*4;
            float4 vq = *(const float4*)&g_Q[qb + (size_t)(q0+r)*DHD + kk + c];
            split_store4(vq, sQh + r*40 + c, sQl + r*40 + c);
            float4 vk = *(const float4*)&g_K[qb + (size_t)(k0+r)*DHD + kk + c];
            split_store4(vk, sKh + r*40 + c, sKl + r*40 + c);
        }
        __syncthreads();
#pragma unroll
        for (int ks=0; ks<2; ks++){
            uint32_t ah[4][4], al[4][4];
#pragma unroll
            for (int mf=0; mf<4; mf++){
                int eo = (wm*64 + mf*16 + arow)*40 + ks*16 + acol;
                ldsm4(ah[mf], qBH + eo*2);
                ldsm4(al[mf], qBL + eo*2);
            }
            uint32_t bhh[2][4], bll[2][4];
#pragma unroll
            for (int p=0;p<2;p++){
                int eo = (wn*32 + p*16 + bnrow)*40 + ks*16 + bkcol;
                ldsm4(bhh[p], kBH + eo*2);
                ldsm4(bll[p], kBL + eo*2);
            }
#pragma unroll
            for (int mf=0;mf<4;mf++)
#pragma unroll
                for (int nf=0;nf<4;nf++){
                    const uint32_t* bhp = &bhh[nf>>1][(nf&1)*2];
                    const uint32_t* blp = &bll[nf>>1][(nf&1)*2];
                    mma16816(acc[mf][nf], ah[mf], bhp);
                    mma16816(acc[mf][nf], ah[mf], blp);
                    mma16816(acc[mf][nf], al[mf], bhp);
                }
        }
        __syncthreads();
    }

    const int g = lane>>2, tt = lane&3;
    float* Sb = g_S + ((size_t)bh<<20);
#pragma unroll
    for (int mf=0;mf<4;mf++){
        const int qr = wm*64 + mf*16 + g;
        const float mq0 = (float)sm_mq[qr];
        const float mq1 = (float)sm_mq[qr+8];
#pragma unroll
        for (int nf=0;nf<4;nf++){
            const int kc = wn*32 + nf*8 + tt*2;
            const float mk0 = (float)sm_mk[kc], mk1 = (float)sm_mk[kc+1];
            float p00 = fmaxf(mq0*mk0,0.f), p01 = fmaxf(mq0*mk1,0.f);
            float p10 = fmaxf(mq1*mk0,0.f), p11 = fmaxf(mq1*mk1,0.f);
            float2 v0{acc[mf][nf][0]*0.125f + (1.f-p00)*NEGV,
                      acc[mf][nf][1]*0.125f + (1.f-p01)*NEGV};
            float2 v1{acc[mf][nf][2]*0.125f + (1.f-p10)*NEGV,
                      acc[mf][nf][3]*0.125f + (1.f-p11)*NEGV};
            *(float2*)&Sb[(size_t)(q0+qr)*SEQ + k0 + kc]     = v0;
            *(float2*)&Sb[(size_t)(q0+qr+8)*SEQ + k0 + kc]   = v1;
        }
    }
}

// ---------------------------------------------------------------------------
// K2b: fused softmax + head-mean. One block per (b,q); loops 16 heads.
// Reads S fp32, writes P fp16 and attn_out fp32.
// ---------------------------------------------------------------------------
__global__ __launch_bounds__(256) void softmax_mean(float* __restrict__ out)
{
    __shared__ float red_m[8], red_s[8];
    const int bq = blockIdx.x;
    const int b = bq>>10, q = bq&1023;
    const int t = threadIdx.x;
    float4 macc{0.f,0.f,0.f,0.f};

#pragma unroll 1
    for (int h=0; h<HH; h++){
        const size_t base = (((size_t)(b*HH+h))<<20) + (size_t)q*SEQ;
        float4 v = *(const float4*)&g_S[base + t*4];
        float m = fmaxf(fmaxf(v.x,v.y), fmaxf(v.z,v.w));
#pragma unroll
        for (int o=16;o>0;o>>=1) m = fmaxf(m, __shfl_xor_sync(0xFFFFFFFFu, m, o));
        if ((t&31)==0) red_m[t>>5] = m;
        __syncthreads();
        m = red_m[0];
#pragma unroll
        for (int i=1;i<8;i++) m = fmaxf(m, red_m[i]);
        v.x = __expf(v.x-m); v.y = __expf(v.y-m);
        v.z = __expf(v.z-m); v.w = __expf(v.w-m);
        float s = v.x+v.y+v.z+v.w;
#pragma unroll
        for (int o=16;o>0;o>>=1) s += __shfl_xor_sync(0xFFFFFFFFu, s, o);
        if ((t&31)==0) red_s[t>>5] = s;
        __syncthreads();
        s = 0.f;
#pragma unroll
        for (int i=0;i<8;i++) s += red_s[i];
        const float inv = 1.0f/s;
        v.x*=inv; v.y*=inv; v.z*=inv; v.w*=inv;
        macc.x += v.x; macc.y += v.y; macc.z += v.z; macc.w += v.w;
        __half2 p0{__float2half_rn(v.x), __float2half_rn(v.y)};
        __half2 p1{__float2half_rn(v.z), __float2half_rn(v.w)};
        *(uint2*)&g_P[base + t*4] = uint2{*(uint32_t*)&p0, *(uint32_t*)&p1};
        __syncthreads();
    }
    const float sc = 1.0f/(float)HH;
    macc.x*=sc; macc.y*=sc; macc.z*=sc; macc.w*=sc;
    *(float4*)&out[(size_t)bq*SEQ + t*4] = macc;
}

// ---------------------------------------------------------------------------
// K2c: O = P(fp16) @ V per bh -> merged heads g_O.  BM=128 BN=64 BK=32.
// P exact fp16 (1 A-operand), V split fp16 hi/lo -> 2 mmas per tile.
// Round-4 style single-buffered loads (no register prefetch).
// ---------------------------------------------------------------------------
__global__ __launch_bounds__(256) void pv_hmma()
{
    __shared__ __align__(16) __half sA[128*40];
    __shared__ __align__(16) __half sBh[32*72], sBl[32*72];
    const int t = threadIdx.x, lane = t&31, wid = t>>5;
    const int bh = blockIdx.y, b = bh>>4, h = bh&15;
    const int q0 = blockIdx.x*128;
    const int wm = wid>>1, wn = wid&1;
    const uint32_t aB = smem_u32(sA);
    const uint32_t bBH = smem_u32(sBh), bBL = smem_u32(sBl);
    const int arow = ((lane>>3)&1)*8 + (lane&7);
    const int acol = (lane>>4)*8;
    const int bkrow = ((lane>>3)&1)*8 + (lane&7);
    const int bnsel = (lane>>4)*8;
    const size_t pb = (size_t)bh<<20;
    const size_t vb = (size_t)bh*SEQ*DHD;

    float acc[2][4][4];
#pragma unroll
    for (int a=0;a<2;a++)
#pragma unroll
        for (int bb=0;bb<4;bb++)
#pragma unroll
            for (int c=0;c<4;c++) acc[a][bb][c]=0.f;

    for (int ck=0; ck<32; ck++){
        const int kk = ck*32;
        // P tile: 128 rows x 32 halfs; 2 uint4 (16 halfs) per thread-pair row
        {
            int r = t>>1, c = (t&1)*16;
            *(uint4*)&sA[r*40 + c]     = *(const uint4*)&g_P[pb + (size_t)(q0+r)*SEQ + kk + c];
            *(uint4*)&sA[r*40 + c + 8] = *(const uint4*)&g_P[pb + (size_t)(q0+r)*SEQ + kk + c + 8];
        }
        // V tile: 32 rows x 64 floats -> fp16 hi/lo
#pragma unroll
        for (int j=0;j<2;j++){
            int i = t + j*256;
            int r = i>>4, c = (i&15)*4;
            float4 v = *(const float4*)&g_V[vb + (size_t)(kk+r)*DHD + c];
            split_store4h(v, sBh + r*72 + c, sBl + r*72 + c);
        }
        __syncthreads();
#pragma unroll
        for (int ks=0; ks<2; ks++){
            uint32_t ah[2][4];
#pragma unroll
            for (int mf=0; mf<2; mf++){
                int eo = (wm*32 + mf*16 + arow)*40 + ks*16 + acol;
                ldsm4(ah[mf], aB + eo*2);
            }
            uint32_t bhh[2][4], bll[2][4];
#pragma unroll
            for (int p=0;p<2;p++){
                int eo = (ks*16 + bkrow)*72 + wn*32 + p*16 + bnsel;
                ldsm4t(bhh[p], bBH + eo*2);
                ldsm4t(bll[p], bBL + eo*2);
            }
#pragma unroll
            for (int mf=0;mf<2;mf++)
#pragma unroll
                for (int nf=0;nf<4;nf++){
                    const uint32_t* bhp = &bhh[nf>>1][(nf&1)*2];
                    const uint32_t* blp = &bll[nf>>1][(nf&1)*2];
                    mma16816h(acc[mf][nf], ah[mf], bhp);
                    mma16816h(acc[mf][nf], ah[mf], blp);
                }
        }
        __syncthreads();
    }

    const int g = lane>>2, tt = lane&3;
#pragma unroll
    for (int mf=0;mf<2;mf++){
        const int q = q0 + wm*32 + mf*16 + g;
        const size_t row0 = ((size_t)(b*SEQ + q))*DM + h*DHD;
#pragma unroll
        for (int nf=0;nf<4;nf++){
            const int d = wn*32 + nf*8 + tt*2;
            *(float2*)&g_O[row0 + d]        = float2{acc[mf][nf][0], acc[mf][nf][1]};
            *(float2*)&g_O[row0 + 8*DM + d] = float2{acc[mf][nf][2], acc[mf][nf][3]};
        }
    }
}

// ---------------------------------------------------------------------------
// K3: out = tokens + O @ Wproj + b (identical to round-4 passing version).
// ---------------------------------------------------------------------------
__global__ __launch_bounds__(256) void proj_hmma(const float* __restrict__ tokens,
                                                 const float* __restrict__ W,
                                                 const float* __restrict__ bias,
                                                 float* __restrict__ out)
{
    __shared__ __align__(16) __nv_bfloat16 sAh[128*40], sAl[128*40];
    __shared__ __align__(16) __nv_bfloat16 sBh[32*136], sBl[32*136];
    const int t = threadIdx.x, lane = t&31, wid = t>>5;
    const int m0 = blockIdx.y*128, n0 = blockIdx.x*128;
    const int wm = wid>>2, wn = wid&3;
    const uint32_t aBH = smem_u32(sAh), aBL = smem_u32(sAl);
    const uint32_t bBH = smem_u32(sBh), bBL = smem_u32(sBl);
    const int arow = ((lane>>3)&1)*8 + (lane&7);
    const int acol = (lane>>4)*8;
    const int bkrow = ((lane>>3)&1)*8 + (lane&7);
    const int bnsel = (lane>>4)*8;

    float acc[4][4][4];
#pragma unroll
    for (int a=0;a<4;a++)
#pragma unroll
        for (int b=0;b<4;b++)
#pragma unroll
            for (int c=0;c<4;c++) acc[a][b][c]=0.f;

    for (int ck=0; ck<32; ck++){
        const int kk = ck*32;
#pragma unroll
        for (int j=0;j<4;j++){
            int i = t + j*256;
            int r = i>>3, c = (i&7)*4;
            float4 v = *(const float4*)&g_O[(size_t)(m0+r)*DM + kk + c];
            split_store4(v, sAh + r*40 + c, sAl + r*40 + c);
        }
#pragma unroll
        for (int j=0;j<4;j++){
            int i = t + j*256;
            int r = i>>5, c = (i&31)*4;
            float4 v = *(const float4*)&W[(size_t)(kk+r)*DM + n0 + c];
            split_store4(v, sBh + r*136 + c, sBl + r*136 + c);
        }
        __syncthreads();
#pragma unroll
        for (int ks=0; ks<2; ks++){
            uint32_t ah[4][4], al[4][4];
#pragma unroll
            for (int mf=0; mf<4; mf++){
                int eo = (wm*64 + mf*16 + arow)*40 + ks*16 + acol;
                ldsm4(ah[mf], aBH + eo*2);
                ldsm4(al[mf], aBL + eo*2);
            }
            uint32_t bh[2][4], bl[2][4];
#pragma unroll
            for (int p=0;p<2;p++){
                int eo = (ks*16 + bkrow)*136 + wn*32 + p*16 + bnsel;
                ldsm4t(bh[p], bBH + eo*2);
                ldsm4t(bl[p], bBL + eo*2);
            }
#pragma unroll
            for (int mf=0;mf<4;mf++)
#pragma unroll
                for (int nf=0;nf<4;nf++){
                    const uint32_t* bhp = &bh[nf>>1][(nf&1)*2];
                    const uint32_t* blp = &bl[nf>>1][(nf&1)*2];
                    mma16816(acc[mf][nf], ah[mf], bhp);
                    mma16816(acc[mf][nf], ah[mf], blp);
                    mma16816(acc[mf][nf], al[mf], bhp);
                }
        }
        __syncthreads();
    }

    const int g = lane>>2, tt = lane&3;
#pragma unroll
    for (int mf=0;mf<4;mf++){
        const int m = m0 + wm*64 + mf*16 + g;
#pragma unroll
        for (int nf=0;nf<4;nf++){
            const int n = n0 + wn*32 + nf*8 + tt*2;
            const float bi0 = bias[n], bi1 = bias[n+1];
            float2 t0 = *(const float2*)&tokens[(size_t)m*DM + n];
            float2 t1 = *(const float2*)&tokens[(size_t)(m+8)*DM + n];
            *(float2*)&out[(size_t)m*DM + n] =
                float2{acc[mf][nf][0]+bi0+t0.x, acc[mf][nf][1]+bi1+t0.y};
            *(float2*)&out[(size_t)(m+8)*DM + n] =
                float2{acc[mf][nf][2]+bi0+t1.x, acc[mf][nf][3]+bi1+t1.y};
        }
    }
}

// ---------------------------------------------------------------------------
extern "C" void kernel_launch(void* const* d_in, const int* in_sizes, int n_in,
                              void* d_out, int out_size)
{
    const float* tokens = (const float*)d_in[0];
    const int*   mask   = (const int*)  d_in[1];
    const float* Wqkv   = (const float*)d_in[2];
    const float* bqkv   = (const float*)d_in[3];
    const float* Wproj  = (const float*)d_in[4];
    const float* bproj  = (const float*)d_in[5];
    float* out = (float*)d_out;

    qkv_hmma<<<dim3(24, 32), 256>>>(tokens, Wqkv, bqkv);
    score_hmma<<<dim3(8, 8, 64), 256>>>(mask);
    softmax_mean<<<4096, 256>>>(out + (size_t)BSZ*SEQ*DM);
    pv_hmma<<<dim3(8, 64), 256>>>();
    proj_hmma<<<dim3(8, 32), 256>>>(tokens, Wproj, bproj, out);
}

// round 9
// speedup vs baseline: 4.3729x; 1.0254x over previous
#include <cuda_runtime.h>
#include <cuda_bf16.h>
#include <cuda_fp16.h>
#include <cstdint>

#define BSZ  4
#define HH   16
#define SEQ  1024
#define DHD  64
#define DM   1024
#define NEGV (-1e9f)

// ---------------- device scratch (allocation-free rule) ----------------
__device__ float  g_Q[64*1024*64];            // [bh][kpos][d] fp32 16MB
__device__ float  g_K[64*1024*64];
__device__ __half g_Vh[64*1024*64];           // V fp16 hi, 8MB
__device__ __half g_Vl[64*1024*64];           // V fp16 lo, 8MB
__device__ float  g_S[(size_t)64*1024*1024];  // [bh][q][k] scores fp32, 256MB
__device__ __half g_P[(size_t)64*1024*1024];  // [bh][q][k] probs fp16, 128MB
__device__ float  g_O[4096*1024];             // [m][h*64+d]  16MB

// ---------------- helpers ----------------
__device__ __forceinline__ uint32_t smem_u32(const void* p){
    uint32_t a;
    asm("{ .reg .u64 t; cvta.to.shared.u64 t, %1; cvt.u32.u64 %0, t; }" : "=r"(a) : "l"(p));
    return a;
}
__device__ __forceinline__ void ldsm4(uint32_t* r, uint32_t addr){
    asm volatile("ldmatrix.sync.aligned.m8n8.x4.shared.b16 {%0,%1,%2,%3}, [%4];"
        : "=r"(r[0]), "=r"(r[1]), "=r"(r[2]), "=r"(r[3]) : "r"(addr));
}
__device__ __forceinline__ void ldsm4t(uint32_t* r, uint32_t addr){
    asm volatile("ldmatrix.sync.aligned.m8n8.x4.trans.shared.b16 {%0,%1,%2,%3}, [%4];"
        : "=r"(r[0]), "=r"(r[1]), "=r"(r[2]), "=r"(r[3]) : "r"(addr));
}
__device__ __forceinline__ void mma16816(float* d, const uint32_t* a, const uint32_t* b){
    asm volatile("mma.sync.aligned.m16n8k16.row.col.f32.bf16.bf16.f32 "
        "{%0,%1,%2,%3}, {%4,%5,%6,%7}, {%8,%9}, {%0,%1,%2,%3};"
        : "+f"(d[0]), "+f"(d[1]), "+f"(d[2]), "+f"(d[3])
        : "r"(a[0]), "r"(a[1]), "r"(a[2]), "r"(a[3]), "r"(b[0]), "r"(b[1]));
}
__device__ __forceinline__ void mma16816h(float* d, const uint32_t* a, const uint32_t* b){
    asm volatile("mma.sync.aligned.m16n8k16.row.col.f32.f16.f16.f32 "
        "{%0,%1,%2,%3}, {%4,%5,%6,%7}, {%8,%9}, {%0,%1,%2,%3};"
        : "+f"(d[0]), "+f"(d[1]), "+f"(d[2]), "+f"(d[3])
        : "r"(a[0]), "r"(a[1]), "r"(a[2]), "r"(a[3]), "r"(b[0]), "r"(b[1]));
}
#define CP_ASYNC16(dst, src) \
    asm volatile("cp.async.ca.shared.global [%0], [%1], 16;" :: "r"(dst), "l"(src) : "memory")
#define CP_COMMIT() asm volatile("cp.async.commit_group;" ::: "memory")
#define CP_WAIT0()  asm volatile("cp.async.wait_group 0;" ::: "memory")
#define CP_WAIT1()  asm volatile("cp.async.wait_group 1;" ::: "memory")

// split fp32x4 -> bf16 hi/lo pairs, 8B stores
__device__ __forceinline__ void split_store4(float4 v, __nv_bfloat16* hi, __nv_bfloat16* lo){
    __nv_bfloat16 h0 = __float2bfloat16_rn(v.x), h1 = __float2bfloat16_rn(v.y);
    __nv_bfloat16 h2 = __float2bfloat16_rn(v.z), h3 = __float2bfloat16_rn(v.w);
    __nv_bfloat16 l0 = __float2bfloat16_rn(v.x - __bfloat162float(h0));
    __nv_bfloat16 l1 = __float2bfloat16_rn(v.y - __bfloat162float(h1));
    __nv_bfloat16 l2 = __float2bfloat16_rn(v.z - __bfloat162float(h2));
    __nv_bfloat16 l3 = __float2bfloat16_rn(v.w - __bfloat162float(h3));
    __nv_bfloat162 hA{h0,h1}, hB{h2,h3}, lA{l0,l1}, lB{l2,l3};
    uint2 hu{*(uint32_t*)&hA, *(uint32_t*)&hB};
    uint2 lu{*(uint32_t*)&lA, *(uint32_t*)&lB};
    *(uint2*)hi = hu;
    *(uint2*)lo = lu;
}

// ---------------------------------------------------------------------------
// K1: QKV GEMM with register-prefetch double buffering.
// Epilogue: Q,K fp32; V split fp16 hi/lo.
// ---------------------------------------------------------------------------
__global__ __launch_bounds__(256) void qkv_hmma(const float* __restrict__ X,
                                                const float* __restrict__ W,
                                                const float* __restrict__ bias)
{
    __shared__ __align__(16) __nv_bfloat16 sAh[128*40], sAl[128*40];
    __shared__ __align__(16) __nv_bfloat16 sBh[32*136], sBl[32*136];
    const int t = threadIdx.x, lane = t&31, wid = t>>5;
    const int m0 = blockIdx.y*128, n0 = blockIdx.x*128;
    const int wm = wid>>2, wn = wid&3;
    const uint32_t aBH = smem_u32(sAh), aBL = smem_u32(sAl);
    const uint32_t bBH = smem_u32(sBh), bBL = smem_u32(sBl);
    const int arow = ((lane>>3)&1)*8 + (lane&7);
    const int acol = (lane>>4)*8;
    const int bkrow = ((lane>>3)&1)*8 + (lane&7);
    const int bnsel = (lane>>4)*8;
    const int rA = t>>3,  cA = (t&7)*4;
    const int rB = t>>5,  cB = (t&31)*4;

    float acc[4][4][4];
#pragma unroll
    for (int a=0;a<4;a++)
#pragma unroll
        for (int b=0;b<4;b++)
#pragma unroll
            for (int c=0;c<4;c++) acc[a][b][c]=0.f;

    float4 pa[4], pb[4];
#pragma unroll
    for (int j=0;j<4;j++){
        pa[j] = *(const float4*)&X[(size_t)(m0+rA+j*32)*DM + cA];
        pb[j] = *(const float4*)&W[(size_t)(rB+j*8)*3072 + n0 + cB];
    }

    for (int ck=0; ck<32; ck++){
#pragma unroll
        for (int j=0;j<4;j++){
            split_store4(pa[j], sAh + (rA+j*32)*40 + cA, sAl + (rA+j*32)*40 + cA);
            split_store4(pb[j], sBh + (rB+j*8)*136 + cB, sBl + (rB+j*8)*136 + cB);
        }
        __syncthreads();
        if (ck < 31){
            const int kk = (ck+1)*32;
#pragma unroll
            for (int j=0;j<4;j++){
                pa[j] = *(const float4*)&X[(size_t)(m0+rA+j*32)*DM + kk + cA];
                pb[j] = *(const float4*)&W[(size_t)(kk+rB+j*8)*3072 + n0 + cB];
            }
        }
#pragma unroll
        for (int ks=0; ks<2; ks++){
            uint32_t ah[4][4], al[4][4];
#pragma unroll
            for (int mf=0; mf<4; mf++){
                int eo = (wm*64 + mf*16 + arow)*40 + ks*16 + acol;
                ldsm4(ah[mf], aBH + eo*2);
                ldsm4(al[mf], aBL + eo*2);
            }
            uint32_t bh[2][4], bl[2][4];
#pragma unroll
            for (int p=0;p<2;p++){
                int eo = (ks*16 + bkrow)*136 + wn*32 + p*16 + bnsel;
                ldsm4t(bh[p], bBH + eo*2);
                ldsm4t(bl[p], bBL + eo*2);
            }
#pragma unroll
            for (int mf=0;mf<4;mf++)
#pragma unroll
                for (int nf=0;nf<4;nf++){
                    const uint32_t* bhp = &bh[nf>>1][(nf&1)*2];
                    const uint32_t* blp = &bl[nf>>1][(nf&1)*2];
                    mma16816(acc[mf][nf], ah[mf], bhp);
                    mma16816(acc[mf][nf], ah[mf], blp);
                    mma16816(acc[mf][nf], al[mf], bhp);
                }
        }
        __syncthreads();
    }

    const int g = lane>>2, tt = lane&3;
#pragma unroll
    for (int mf=0;mf<4;mf++){
        const int m = m0 + wm*64 + mf*16 + g;
        const int b = m>>10, kpos = m&1023;
#pragma unroll
        for (int nf=0;nf<4;nf++){
            const int n = n0 + wn*32 + nf*8 + tt*2;
            const int which = n>>10, h = (n>>6)&15, d = n&63;
            const size_t base0 = (((size_t)(b*HH+h))*SEQ + kpos)*DHD + d;
            const float bi0 = bias[n], bi1 = bias[n+1];
            const float v0 = acc[mf][nf][0]+bi0, v1 = acc[mf][nf][1]+bi1;
            const float v2 = acc[mf][nf][2]+bi0, v3 = acc[mf][nf][3]+bi1;
            if (which == 2){
                __half h0=__float2half_rn(v0), h1=__float2half_rn(v1);
                __half h2=__float2half_rn(v2), h3=__float2half_rn(v3);
                __half l0=__float2half_rn(v0-__half2float(h0));
                __half l1=__float2half_rn(v1-__half2float(h1));
                __half l2=__float2half_rn(v2-__half2float(h2));
                __half l3=__float2half_rn(v3-__half2float(h3));
                *(__half2*)&g_Vh[base0]         = __half2{h0,h1};
                *(__half2*)&g_Vh[base0+8*DHD]   = __half2{h2,h3};
                *(__half2*)&g_Vl[base0]         = __half2{l0,l1};
                *(__half2*)&g_Vl[base0+8*DHD]   = __half2{l2,l3};
            } else {
                float* dst = which==0 ? g_Q : g_K;
                *(float2*)&dst[base0]         = float2{v0, v1};
                *(float2*)&dst[base0 + 8*DHD] = float2{v2, v3};
            }
        }
    }
}

// ---------------------------------------------------------------------------
// K2a: scores S = (Q K^T)/8 + mask (identical to round-8 passing version).
// ---------------------------------------------------------------------------
__global__ __launch_bounds__(256) void score_hmma(const int* __restrict__ mask)
{
    __shared__ __align__(16) __nv_bfloat16 sQh[128*40], sQl[128*40];
    __shared__ __align__(16) __nv_bfloat16 sKh[128*40], sKl[128*40];
    __shared__ int sm_mq[128], sm_mk[128];

    const int t = threadIdx.x, lane = t&31, wid = t>>5;
    const int bh = blockIdx.z, b = bh>>4;
    const int q0 = blockIdx.y*128, k0 = blockIdx.x*128;
    const int wm = wid>>2, wn = wid&3;
    const uint32_t qBH = smem_u32(sQh), qBL = smem_u32(sQl);
    const uint32_t kBH = smem_u32(sKh), kBL = smem_u32(sKl);

    if (t < 128){ sm_mq[t] = mask[b*SEQ + q0 + t]; }
    else        { sm_mk[t-128] = mask[b*SEQ + k0 + (t-128)]; }

    const size_t qb = (size_t)bh*SEQ*DHD;
    const int arow = ((lane>>3)&1)*8 + (lane&7);
    const int acol = (lane>>4)*8;
    const int bnrow = (lane>=16?8:0) + (lane&7);
    const int bkcol = ((lane>>3)&1)*8;

    float acc[4][4][4];
#pragma unroll
    for (int a=0;a<4;a++)
#pragma unroll
        for (int bb=0;bb<4;bb++)
#pragma unroll
            for (int c=0;c<4;c++) acc[a][bb][c]=0.f;

#pragma unroll
    for (int ck=0; ck<2; ck++){
        const int kk = ck*32;
#pragma unroll
        for (int j=0;j<4;j++){
            int i = t + j*256;
            int r = i>>3, c = (i&7)*4;
            float4 vq = *(const float4*)&g_Q[qb + (size_t)(q0+r)*DHD + kk + c];
            split_store4(vq, sQh + r*40 + c, sQl + r*40 + c);
            float4 vk = *(const float4*)&g_K[qb + (size_t)(k0+r)*DHD + kk + c];
            split_store4(vk, sKh + r*40 + c, sKl + r*40 + c);
        }
        __syncthreads();
#pragma unroll
        for (int ks=0; ks<2; ks++){
            uint32_t ah[4][4], al[4][4];
#pragma unroll
            for (int mf=0; mf<4; mf++){
                int eo = (wm*64 + mf*16 + arow)*40 + ks*16 + acol;
                ldsm4(ah[mf], qBH + eo*2);
                ldsm4(al[mf], qBL + eo*2);
            }
            uint32_t bhh[2][4], bll[2][4];
#pragma unroll
            for (int p=0;p<2;p++){
                int eo = (wn*32 + p*16 + bnrow)*40 + ks*16 + bkcol;
                ldsm4(bhh[p], kBH + eo*2);
                ldsm4(bll[p], kBL + eo*2);
            }
#pragma unroll
            for (int mf=0;mf<4;mf++)
#pragma unroll
                for (int nf=0;nf<4;nf++){
                    const uint32_t* bhp = &bhh[nf>>1][(nf&1)*2];
                    const uint32_t* blp = &bll[nf>>1][(nf&1)*2];
                    mma16816(acc[mf][nf], ah[mf], bhp);
                    mma16816(acc[mf][nf], ah[mf], blp);
                    mma16816(acc[mf][nf], al[mf], bhp);
                }
        }
        __syncthreads();
    }

    const int g = lane>>2, tt = lane&3;
    float* Sb = g_S + ((size_t)bh<<20);
#pragma unroll
    for (int mf=0;mf<4;mf++){
        const int qr = wm*64 + mf*16 + g;
        const float mq0 = (float)sm_mq[qr];
        const float mq1 = (float)sm_mq[qr+8];
#pragma unroll
        for (int nf=0;nf<4;nf++){
            const int kc = wn*32 + nf*8 + tt*2;
            const float mk0 = (float)sm_mk[kc], mk1 = (float)sm_mk[kc+1];
            float p00 = fmaxf(mq0*mk0,0.f), p01 = fmaxf(mq0*mk1,0.f);
            float p10 = fmaxf(mq1*mk0,0.f), p11 = fmaxf(mq1*mk1,0.f);
            float2 v0{acc[mf][nf][0]*0.125f + (1.f-p00)*NEGV,
                      acc[mf][nf][1]*0.125f + (1.f-p01)*NEGV};
            float2 v1{acc[mf][nf][2]*0.125f + (1.f-p10)*NEGV,
                      acc[mf][nf][3]*0.125f + (1.f-p11)*NEGV};
            *(float2*)&Sb[(size_t)(q0+qr)*SEQ + k0 + kc]     = v0;
            *(float2*)&Sb[(size_t)(q0+qr+8)*SEQ + k0 + kc]   = v1;
        }
    }
}

// ---------------------------------------------------------------------------
// K2b: fused softmax + head-mean, with next-head register prefetch.
// ---------------------------------------------------------------------------
__global__ __launch_bounds__(256) void softmax_mean(float* __restrict__ out)
{
    __shared__ float red_m[8], red_s[8];
    const int bq = blockIdx.x;
    const int b = bq>>10, q = bq&1023;
    const int t = threadIdx.x;
    float4 macc{0.f,0.f,0.f,0.f};

    const size_t base0 = (((size_t)(b*HH))<<20) + (size_t)q*SEQ + t*4;
    float4 v = *(const float4*)&g_S[base0];

#pragma unroll 1
    for (int h=0; h<HH; h++){
        float4 vn;
        if (h < HH-1) vn = *(const float4*)&g_S[base0 + ((size_t)(h+1)<<20)];
        float m = fmaxf(fmaxf(v.x,v.y), fmaxf(v.z,v.w));
#pragma unroll
        for (int o=16;o>0;o>>=1) m = fmaxf(m, __shfl_xor_sync(0xFFFFFFFFu, m, o));
        if ((t&31)==0) red_m[t>>5] = m;
        __syncthreads();
        m = red_m[0];
#pragma unroll
        for (int i=1;i<8;i++) m = fmaxf(m, red_m[i]);
        v.x = __expf(v.x-m); v.y = __expf(v.y-m);
        v.z = __expf(v.z-m); v.w = __expf(v.w-m);
        float s = v.x+v.y+v.z+v.w;
#pragma unroll
        for (int o=16;o>0;o>>=1) s += __shfl_xor_sync(0xFFFFFFFFu, s, o);
        if ((t&31)==0) red_s[t>>5] = s;
        __syncthreads();
        s = 0.f;
#pragma unroll
        for (int i=0;i<8;i++) s += red_s[i];
        const float inv = 1.0f/s;
        v.x*=inv; v.y*=inv; v.z*=inv; v.w*=inv;
        macc.x += v.x; macc.y += v.y; macc.z += v.z; macc.w += v.w;
        __half2 p0{__float2half_rn(v.x), __float2half_rn(v.y)};
        __half2 p1{__float2half_rn(v.z), __float2half_rn(v.w)};
        *(uint2*)&g_P[base0 + ((size_t)h<<20)] = uint2{*(uint32_t*)&p0, *(uint32_t*)&p1};
        v = vn;
        __syncthreads();
    }
    const float sc = 1.0f/(float)HH;
    macc.x*=sc; macc.y*=sc; macc.z*=sc; macc.w*=sc;
    *(float4*)&out[(size_t)bq*SEQ + t*4] = macc;
}

// ---------------------------------------------------------------------------
// K2c: O = P(fp16) @ V per bh, cp.async 2-stage ping-pong pipeline.
// P exact fp16; V pre-split fp16 hi/lo -> 2 mmas per tile.
// ---------------------------------------------------------------------------
__global__ __launch_bounds__(256) void pv_hmma()
{
    __shared__ __align__(16) __half sA[2][128*40];
    __shared__ __align__(16) __half sBh[2][32*72], sBl[2][32*72];
    const int t = threadIdx.x, lane = t&31, wid = t>>5;
    const int bh = blockIdx.y, b = bh>>4, h = bh&15;
    const int q0 = blockIdx.x*128;
    const int wm = wid>>1, wn = wid&1;
    const uint32_t aB0 = smem_u32(sA[0]),  aB1 = smem_u32(sA[1]);
    const uint32_t bH0 = smem_u32(sBh[0]), bH1 = smem_u32(sBh[1]);
    const uint32_t bL0 = smem_u32(sBl[0]), bL1 = smem_u32(sBl[1]);
    const int arow = ((lane>>3)&1)*8 + (lane&7);
    const int acol = (lane>>4)*8;
    const int bkrow = ((lane>>3)&1)*8 + (lane&7);
    const int bnsel = (lane>>4)*8;
    const size_t pb = (size_t)bh<<20;
    const size_t vb = (size_t)bh*SEQ*DHD;
    const int rP = t>>1, cP = (t&1)*16;     // P tile 128x32 halfs
    const int rV = t>>3, cV8 = (t&7)*8;     // V tiles 32x64 halfs

    float acc[2][4][4];
#pragma unroll
    for (int a=0;a<2;a++)
#pragma unroll
        for (int bb=0;bb<4;bb++)
#pragma unroll
            for (int c=0;c<4;c++) acc[a][bb][c]=0.f;

    auto issue = [&](int ck, uint32_t aB, uint32_t bH, uint32_t bL){
        const int kk = ck*32;
        const __half* gp = &g_P[pb + (size_t)(q0+rP)*SEQ + kk + cP];
        CP_ASYNC16(aB + (rP*40 + cP)*2,     gp);
        CP_ASYNC16(aB + (rP*40 + cP + 8)*2, gp + 8);
        CP_ASYNC16(bH + (rV*72 + cV8)*2, &g_Vh[vb + (size_t)(kk+rV)*DHD + cV8]);
        CP_ASYNC16(bL + (rV*72 + cV8)*2, &g_Vl[vb + (size_t)(kk+rV)*DHD + cV8]);
        CP_COMMIT();
    };

    issue(0, aB0, bH0, bL0);

    for (int ck=0; ck<32; ck++){
        if (ck < 31){
            if (ck & 1) issue(ck+1, aB0, bH0, bL0);
            else        issue(ck+1, aB1, bH1, bL1);
            CP_WAIT1();
        } else {
            CP_WAIT0();
        }
        __syncthreads();
        const uint32_t aB = (ck&1) ? aB1 : aB0;
        const uint32_t bH = (ck&1) ? bH1 : bH0;
        const uint32_t bL = (ck&1) ? bL1 : bL0;
#pragma unroll
        for (int ks=0; ks<2; ks++){
            uint32_t ah[2][4];
#pragma unroll
            for (int mf=0; mf<2; mf++){
                int eo = (wm*32 + mf*16 + arow)*40 + ks*16 + acol;
                ldsm4(ah[mf], aB + eo*2);
            }
            uint32_t bhh[2][4], bll[2][4];
#pragma unroll
            for (int p=0;p<2;p++){
                int eo = (ks*16 + bkrow)*72 + wn*32 + p*16 + bnsel;
                ldsm4t(bhh[p], bH + eo*2);
                ldsm4t(bll[p], bL + eo*2);
            }
#pragma unroll
            for (int mf=0;mf<2;mf++)
#pragma unroll
                for (int nf=0;nf<4;nf++){
                    const uint32_t* bhp = &bhh[nf>>1][(nf&1)*2];
                    const uint32_t* blp = &bll[nf>>1][(nf&1)*2];
                    mma16816h(acc[mf][nf], ah[mf], bhp);
                    mma16816h(acc[mf][nf], ah[mf], blp);
                }
        }
        __syncthreads();
    }

    const int g = lane>>2, tt = lane&3;
#pragma unroll
    for (int mf=0;mf<2;mf++){
        const int q = q0 + wm*32 + mf*16 + g;
        const size_t row0 = ((size_t)(b*SEQ + q))*DM + h*DHD;
#pragma unroll
        for (int nf=0;nf<4;nf++){
            const int d = wn*32 + nf*8 + tt*2;
            *(float2*)&g_O[row0 + d]        = float2{acc[mf][nf][0], acc[mf][nf][1]};
            *(float2*)&g_O[row0 + 8*DM + d] = float2{acc[mf][nf][2], acc[mf][nf][3]};
        }
    }
}

// ---------------------------------------------------------------------------
// K3: out = tokens + O @ Wproj + b, register-prefetch double buffering.
// ---------------------------------------------------------------------------
__global__ __launch_bounds__(256) void proj_hmma(const float* __restrict__ tokens,
                                                 const float* __restrict__ W,
                                                 const float* __restrict__ bias,
                                                 float* __restrict__ out)
{
    __shared__ __align__(16) __nv_bfloat16 sAh[128*40], sAl[128*40];
    __shared__ __align__(16) __nv_bfloat16 sBh[32*136], sBl[32*136];
    const int t = threadIdx.x, lane = t&31, wid = t>>5;
    const int m0 = blockIdx.y*128, n0 = blockIdx.x*128;
    const int wm = wid>>2, wn = wid&3;
    const uint32_t aBH = smem_u32(sAh), aBL = smem_u32(sAl);
    const uint32_t bBH = smem_u32(sBh), bBL = smem_u32(sBl);
    const int arow = ((lane>>3)&1)*8 + (lane&7);
    const int acol = (lane>>4)*8;
    const int bkrow = ((lane>>3)&1)*8 + (lane&7);
    const int bnsel = (lane>>4)*8;
    const int rA = t>>3, cA = (t&7)*4;
    const int rB = t>>5, cB = (t&31)*4;

    float acc[4][4][4];
#pragma unroll
    for (int a=0;a<4;a++)
#pragma unroll
        for (int b=0;b<4;b++)
#pragma unroll
            for (int c=0;c<4;c++) acc[a][b][c]=0.f;

    float4 pa[4], pb[4];
#pragma unroll
    for (int j=0;j<4;j++){
        pa[j] = *(const float4*)&g_O[(size_t)(m0+rA+j*32)*DM + cA];
        pb[j] = *(const float4*)&W[(size_t)(rB+j*8)*DM + n0 + cB];
    }

    for (int ck=0; ck<32; ck++){
#pragma unroll
        for (int j=0;j<4;j++){
            split_store4(pa[j], sAh + (rA+j*32)*40 + cA, sAl + (rA+j*32)*40 + cA);
            split_store4(pb[j], sBh + (rB+j*8)*136 + cB, sBl + (rB+j*8)*136 + cB);
        }
        __syncthreads();
        if (ck < 31){
            const int kk = (ck+1)*32;
#pragma unroll
            for (int j=0;j<4;j++){
                pa[j] = *(const float4*)&g_O[(size_t)(m0+rA+j*32)*DM + kk + cA];
                pb[j] = *(const float4*)&W[(size_t)(kk+rB+j*8)*DM + n0 + cB];
            }
        }
#pragma unroll
        for (int ks=0; ks<2; ks++){
            uint32_t ah[4][4], al[4][4];
#pragma unroll
            for (int mf=0; mf<4; mf++){
                int eo = (wm*64 + mf*16 + arow)*40 + ks*16 + acol;
                ldsm4(ah[mf], aBH + eo*2);
                ldsm4(al[mf], aBL + eo*2);
            }
            uint32_t bh[2][4], bl[2][4];
#pragma unroll
            for (int p=0;p<2;p++){
                int eo = (ks*16 + bkrow)*136 + wn*32 + p*16 + bnsel;
                ldsm4t(bh[p], bBH + eo*2);
                ldsm4t(bl[p], bBL + eo*2);
            }
#pragma unroll
            for (int mf=0;mf<4;mf++)
#pragma unroll
                for (int nf=0;nf<4;nf++){
                    const uint32_t* bhp = &bh[nf>>1][(nf&1)*2];
                    const uint32_t* blp = &bl[nf>>1][(nf&1)*2];
                    mma16816(acc[mf][nf], ah[mf], bhp);
                    mma16816(acc[mf][nf], ah[mf], blp);
                    mma16816(acc[mf][nf], al[mf], bhp);
                }
        }
        __syncthreads();
    }

    const int g = lane>>2, tt = lane&3;
#pragma unroll
    for (int mf=0;mf<4;mf++){
        const int m = m0 + wm*64 + mf*16 + g;
#pragma unroll
        for (int nf=0;nf<4;nf++){
            const int n = n0 + wn*32 + nf*8 + tt*2;
            const float bi0 = bias[n], bi1 = bias[n+1];
            float2 t0 = *(const float2*)&tokens[(size_t)m*DM + n];
            float2 t1 = *(const float2*)&tokens[(size_t)(m+8)*DM + n];
            *(float2*)&out[(size_t)m*DM + n] =
                float2{acc[mf][nf][0]+bi0+t0.x, acc[mf][nf][1]+bi1+t0.y};
            *(float2*)&out[(size_t)(m+8)*DM + n] =
                float2{acc[mf][nf][2]+bi0+t1.x, acc[mf][nf][3]+bi1+t1.y};
        }
    }
}

// ---------------------------------------------------------------------------
extern "C" void kernel_launch(void* const* d_in, const int* in_sizes, int n_in,
                              void* d_out, int out_size)
{
    const float* tokens = (const float*)d_in[0];
    const int*   mask   = (const int*)  d_in[1];
    const float* Wqkv   = (const float*)d_in[2];
    const float* bqkv   = (const float*)d_in[3];
    const float* Wproj  = (const float*)d_in[4];
    const float* bproj  = (const float*)d_in[5];
    float* out = (float*)d_out;

    qkv_hmma<<<dim3(24, 32), 256>>>(tokens, Wqkv, bqkv);
    score_hmma<<<dim3(8, 8, 64), 256>>>(mask);
    softmax_mean<<<4096, 256>>>(out + (size_t)BSZ*SEQ*DM);
    pv_hmma<<<dim3(8, 64), 256>>>();
    proj_hmma<<<dim3(8, 32), 256>>>(tokens, Wproj, bproj, out);
}